// round 1
// baseline (speedup 1.0000x reference)
#include <cuda_runtime.h>
#include <cuda_bf16.h>

// Problem constants
#define SDIM   785          // seq incl. CLS
#define NP     784          // LayerNorm width (columns 1..784)
#define NL     12
#define NB     4
#define NH     12
#define NSLAB  (NL*NB*NH)   // 576 slabs of [785,785]
#define KTH    588          // kth smallest (1-based)
#define LN_EPS 1e-5f
#define ROWS_PER_CHUNK 392  // NP/2, divisible by 4

// Scratch accumulator: s_raw[b][c] = sum over (l,h,i) of att[l,b,h,i+? ,c+1]
__device__ float g_sums[NB * NP];

// ---------------------------------------------------------------------------
// Kernel 0: zero the scratch (graph replays re-run this every launch)
// ---------------------------------------------------------------------------
__global__ void zero_kernel() {
    int i = blockIdx.x * blockDim.x + threadIdx.x;
    if (i < NB * NP) g_sums[i] = 0.0f;
}

// ---------------------------------------------------------------------------
// Kernel 1: streaming column-sum over the 1.42 GB tensor.
// grid = (4 column-blocks, 2 row-chunks, 576 slabs), block = 256 threads.
// Thread owns one column c (maps to j = c+1), sums rows i = 1..784 of its
// row-chunk with 4 independent accumulators, then one atomicAdd.
// ---------------------------------------------------------------------------
__global__ __launch_bounds__(256) void colsum_kernel(const float* __restrict__ att) {
    const int m = blockIdx.z;                       // slab: l*48 + b*12 + h
    const int b = (m / NH) % NB;
    const int c = blockIdx.x * blockDim.x + threadIdx.x;
    if (c >= NP) return;

    const float* base = att + (size_t)m * ((size_t)SDIM * SDIM);
    const int r0 = 1 + blockIdx.y * ROWS_PER_CHUNK;

    const float* p = base + (size_t)r0 * SDIM + (c + 1);
    float a0 = 0.f, a1 = 0.f, a2 = 0.f, a3 = 0.f;
    #pragma unroll 1
    for (int it = 0; it < ROWS_PER_CHUNK / 4; ++it) {
        a0 += __ldcs(p);
        a1 += __ldcs(p + SDIM);
        a2 += __ldcs(p + 2 * SDIM);
        a3 += __ldcs(p + 3 * SDIM);
        p += 4 * SDIM;
    }
    atomicAdd(&g_sums[b * NP + c], (a0 + a1) + (a2 + a3));
}

// ---------------------------------------------------------------------------
// Kernel 2: LayerNorm + sigmoid + exact kth-smallest threshold + mask.
// One block per batch row, 1024 threads.
// ---------------------------------------------------------------------------
__device__ __forceinline__ float block_reduce_sum(float v, float* red) {
    // 1024 threads = 32 warps
    #pragma unroll
    for (int o = 16; o > 0; o >>= 1)
        v += __shfl_xor_sync(0xFFFFFFFFu, v, o);
    const int wid = threadIdx.x >> 5;
    const int lid = threadIdx.x & 31;
    if (lid == 0) red[wid] = v;
    __syncthreads();
    if (wid == 0) {
        v = red[lid];
        #pragma unroll
        for (int o = 16; o > 0; o >>= 1)
            v += __shfl_xor_sync(0xFFFFFFFFu, v, o);
        if (lid == 0) red[0] = v;
    }
    __syncthreads();
    float r = red[0];
    __syncthreads();
    return r;
}

__global__ __launch_bounds__(1024) void finalize_kernel(const float* __restrict__ gamma,
                                                        const float* __restrict__ beta,
                                                        float* __restrict__ out) {
    __shared__ float sp[NP];
    __shared__ float red[32];
    __shared__ float s_thr;

    const int b = blockIdx.x;
    const int t = threadIdx.x;
    const bool active = (t < NP);

    float s = 0.0f;
    if (active) s = g_sums[b * NP + t] * (1.0f / 144.0f);

    // mean
    float total = block_reduce_sum(active ? s : 0.0f, red);
    const float mu = total * (1.0f / (float)NP);

    // variance (two-pass, matches reference formula)
    float d = active ? (s - mu) : 0.0f;
    float ss = block_reduce_sum(d * d, red);
    const float rstd = rsqrtf(ss * (1.0f / (float)NP) + LN_EPS);

    // ln -> sigmoid -> shared
    if (active) {
        float ln = d * rstd * gamma[t] + beta[t];
        float p  = 1.0f / (1.0f + expf(-ln));
        sp[t] = p;
    }
    __syncthreads();

    // exact kth smallest via rank counting: v is the KTH-smallest iff
    // (#{x < v} < KTH) && (#{x <= v} >= KTH). Ties write identical bits.
    if (active) {
        const float v = sp[t];
        int lt = 0, le = 0;
        #pragma unroll 4
        for (int u = 0; u < NP; ++u) {
            const float x = sp[u];        // broadcast read, conflict-free
            lt += (x <  v);
            le += (x <= v);
        }
        if (lt < KTH && le >= KTH) s_thr = v;
    }
    __syncthreads();

    if (active) {
        out[b * NP + t] = (sp[t] > s_thr) ? 1.0f : 0.0f;
    }
}

// ---------------------------------------------------------------------------
// Launch contract
// ---------------------------------------------------------------------------
extern "C" void kernel_launch(void* const* d_in, const int* in_sizes, int n_in,
                              void* d_out, int out_size) {
    const float* att   = (const float*)d_in[0];   // [12,4,12,785,785] f32
    const float* gamma = (const float*)d_in[1];   // [784] f32
    const float* beta  = (const float*)d_in[2];   // [784] f32
    float* out = (float*)d_out;                   // [4,784] f32

    zero_kernel<<<(NB * NP + 255) / 256, 256>>>();

    dim3 grid((NP + 255) / 256, 2, NSLAB);        // 4 x 2 x 576 blocks
    colsum_kernel<<<grid, 256>>>(att);

    finalize_kernel<<<NB, 1024>>>(gamma, beta, out);
}

// round 2
// speedup vs baseline: 1.1347x; 1.1347x over previous
#include <cuda_runtime.h>
#include <cuda_bf16.h>

// Problem constants
#define SDIM     785          // seq incl. CLS
#define SLABSZ   616225       // 785*785
#define NP       784
#define NL       12
#define NB       4
#define NH       12
#define NSLAB    (NL*NB*NH)   // 576
#define KTH      588
#define LN_EPS   1e-5f
#define CHUNKS   4            // group-chunks per slab in the vector kernel
#define GPC      49           // max groups per chunk (196/4)

// Scratch accumulator: g_sums[b][c] for column j = c+1
__device__ float g_sums[NB * NP];

// ---------------------------------------------------------------------------
// Kernel 0: zero scratch (re-run every graph replay)
// ---------------------------------------------------------------------------
__global__ void zero_kernel() {
    int i = blockIdx.x * blockDim.x + threadIdx.x;
    if (i < NB * NP) g_sums[i] = 0.0f;
}

// ---------------------------------------------------------------------------
// Kernel 1: vectorized column-sum.
// Rows are processed in 4-row groups whose first row r satisfies
// (m + r) % 4 == 0, so the per-row float alignment shifts are statically
// {0,1,2,3}. Every load is an aligned LDG.128. Thread t owns float4 slot t
// of the row window; element (lane e, shift s) maps to column 4t + e - s,
// i.e. accumulator d = e - s + 3 in a fixed 7-wide window [4t-3, 4t+3].
// Threads t in [0,196] are active (197*4 = 788 >= 785+3).
// ---------------------------------------------------------------------------
__global__ __launch_bounds__(224) void colsum_vec(const float* __restrict__ att) {
    const int blk   = blockIdx.x;           // 0 .. NSLAB*CHUNKS-1
    const int chunk = blk & (CHUNKS - 1);
    const int m     = blk >> 2;             // slab 0..575
    const int t     = threadIdx.x;
    if (t > 196) return;

    const int b       = (m / NH) & 3;       // m = l*48 + b*12 + h
    const int r_first = (4 - (m & 3)) & 3;  // first row with shift 0
    const int Gm      = (785 - r_first) >> 2;  // 195 or 196 groups
    const int g0      = chunk * GPC;
    int gcnt = Gm - g0;
    if (gcnt <= 0) return;
    if (gcnt > GPC) gcnt = GPC;

    const float* fp = att + (size_t)m * SLABSZ
                          + (size_t)(r_first + 4 * g0) * SDIM;   // 16B-aligned

    float a0 = 0.f, a1 = 0.f, a2 = 0.f, a3 = 0.f, a4 = 0.f, a5 = 0.f, a6 = 0.f;

    #pragma unroll 2
    for (int g = 0; g < gcnt; ++g) {
        const float4 x = __ldcs((const float4*)(fp)        + t);  // shift 0
        const float4 y = __ldcs((const float4*)(fp +  784) + t);  // shift 1
        const float4 z = __ldcs((const float4*)(fp + 1568) + t);  // shift 2
        const float4 w = __ldcs((const float4*)(fp + 2352) + t);  // shift 3

        a3 += x.x; a4 += x.y; a5 += x.z; a6 += x.w;   // cols 4t .. 4t+3
        a2 += y.x; a3 += y.y; a4 += y.z; a5 += y.w;   // cols 4t-1 .. 4t+2
        a1 += z.x; a2 += z.y; a3 += z.z; a4 += z.w;   // cols 4t-2 .. 4t+1
        a0 += w.x; a1 += w.y; a2 += w.z; a3 += w.w;   // cols 4t-3 .. 4t
        fp += 4 * SDIM;                               // 3140 floats, aligned
    }

    const float acc[7] = {a0, a1, a2, a3, a4, a5, a6};
    const int cbase = 4 * t - 3;
    float* gs = &g_sums[b * NP];
    #pragma unroll
    for (int d = 0; d < 7; ++d) {
        const int c = cbase + d;              // column j in [1,784] is valid
        if (c >= 1 && c <= NP) atomicAdd(&gs[c - 1], acc[d]);
    }
}

// ---------------------------------------------------------------------------
// Kernel 1b: signed correction for rows not covered by aligned groups.
//   m%4==0: groups cover rows 0..783  -> subtract row 0, add row 784
//   m%4==1: cover 3..782              -> add rows 1,2,783,784
//   m%4==2: cover 2..781              -> add rows 1,782,783,784
//   m%4==3: cover 1..784              -> nothing
// ---------------------------------------------------------------------------
__global__ __launch_bounds__(256) void correction_kernel(const float* __restrict__ att) {
    const int m  = blockIdx.x;
    const int mm = m & 3;
    if (mm == 3) return;
    const int b = (m / NH) & 3;
    const float* base = att + (size_t)m * SLABSZ;

    int   rows[4];
    float sgn[4];
    int   n;
    if (mm == 0)      { rows[0] = 0; sgn[0] = -1.f; rows[1] = 784; sgn[1] = 1.f; n = 2; }
    else if (mm == 1) { rows[0] = 1; rows[1] = 2;   rows[2] = 783; rows[3] = 784;
                        sgn[0] = sgn[1] = sgn[2] = sgn[3] = 1.f; n = 4; }
    else              { rows[0] = 1; rows[1] = 782; rows[2] = 783; rows[3] = 784;
                        sgn[0] = sgn[1] = sgn[2] = sgn[3] = 1.f; n = 4; }

    for (int c = threadIdx.x; c < NP; c += blockDim.x) {
        float s = 0.f;
        for (int i = 0; i < n; ++i)
            s += sgn[i] * __ldg(base + (size_t)rows[i] * SDIM + (c + 1));
        atomicAdd(&g_sums[b * NP + c], s);
    }
}

// ---------------------------------------------------------------------------
// Kernel 2: LayerNorm + sigmoid + exact kth-smallest + mask.
// ---------------------------------------------------------------------------
__device__ __forceinline__ float block_reduce_sum(float v, float* red) {
    #pragma unroll
    for (int o = 16; o > 0; o >>= 1) v += __shfl_xor_sync(0xFFFFFFFFu, v, o);
    const int wid = threadIdx.x >> 5, lid = threadIdx.x & 31;
    if (lid == 0) red[wid] = v;
    __syncthreads();
    if (wid == 0) {
        v = red[lid];
        #pragma unroll
        for (int o = 16; o > 0; o >>= 1) v += __shfl_xor_sync(0xFFFFFFFFu, v, o);
        if (lid == 0) red[0] = v;
    }
    __syncthreads();
    float r = red[0];
    __syncthreads();
    return r;
}

__global__ __launch_bounds__(1024) void finalize_kernel(const float* __restrict__ gamma,
                                                        const float* __restrict__ beta,
                                                        float* __restrict__ out) {
    __shared__ float sp[NP];
    __shared__ float red[32];
    __shared__ float s_thr;

    const int b = blockIdx.x;
    const int t = threadIdx.x;
    const bool active = (t < NP);

    float s = active ? g_sums[b * NP + t] * (1.0f / 144.0f) : 0.0f;

    const float mu = block_reduce_sum(s, red) * (1.0f / (float)NP);
    float d = active ? (s - mu) : 0.0f;
    const float rstd = rsqrtf(block_reduce_sum(d * d, red) * (1.0f / (float)NP) + LN_EPS);

    if (active) {
        float ln = d * rstd * gamma[t] + beta[t];
        sp[t] = 1.0f / (1.0f + expf(-ln));
    }
    __syncthreads();

    if (active) {
        const float v = sp[t];
        int lt = 0, le = 0;
        #pragma unroll 4
        for (int u = 0; u < NP; ++u) {
            const float x = sp[u];
            lt += (x <  v);
            le += (x <= v);
        }
        if (lt < KTH && le >= KTH) s_thr = v;   // exact kth smallest (ties safe)
    }
    __syncthreads();

    if (active) out[b * NP + t] = (sp[t] > s_thr) ? 1.0f : 0.0f;
}

// ---------------------------------------------------------------------------
// Launch contract
// ---------------------------------------------------------------------------
extern "C" void kernel_launch(void* const* d_in, const int* in_sizes, int n_in,
                              void* d_out, int out_size) {
    const float* att   = (const float*)d_in[0];   // [12,4,12,785,785] f32
    const float* gamma = (const float*)d_in[1];   // [784] f32
    const float* beta  = (const float*)d_in[2];   // [784] f32
    float* out = (float*)d_out;                   // [4,784] f32

    zero_kernel<<<(NB * NP + 255) / 256, 256>>>();
    colsum_vec<<<NSLAB * CHUNKS, 224>>>(att);
    correction_kernel<<<NSLAB, 256>>>(att);
    finalize_kernel<<<NB, 1024>>>(gamma, beta, out);
}

// round 3
// speedup vs baseline: 1.3022x; 1.1477x over previous
#include <cuda_runtime.h>
#include <cuda_bf16.h>

// Problem constants
#define SDIM     785          // seq incl. CLS
#define SLABSZ   616225       // 785*785
#define NP       784
#define NL       12
#define NB       4
#define NH       12
#define NSLAB    (NL*NB*NH)   // 576
#define KTH      588
#define LN_EPS   1e-5f
#define CHUNKS   4
#define GPC      49           // groups per chunk

// Scratch accumulator: g_sums[b][c] for column j = c+1
__device__ float g_sums[NB * NP];

// ---------------------------------------------------------------------------
// Kernel 0: zero scratch (re-run every graph replay)
// ---------------------------------------------------------------------------
__global__ void zero_kernel() {
    int i = blockIdx.x * blockDim.x + threadIdx.x;
    if (i < NB * NP) g_sums[i] = 0.0f;
}

// ---------------------------------------------------------------------------
// Kernel 1: vectorized column-sum + merged edge-row correction.
// 4-row groups start at rows with (m + r) % 4 == 0 so per-row float shifts
// are statically {0,1,2,3}: every load is an aligned LDG.128. Thread t owns
// float4 slot t; element (lane e, shift s) -> column 4t + e - s, accumulator
// d = e - s + 3 in a fixed 7-wide window [4t-3, 4t+3].
// The chunk-3 block of each slab additionally applies the signed correction
// for rows not covered by aligned groups.
// ---------------------------------------------------------------------------
__global__ __launch_bounds__(224) void colsum_vec(const float* __restrict__ att) {
    const int blk   = blockIdx.x;           // 0 .. NSLAB*CHUNKS-1
    const int chunk = blk & (CHUNKS - 1);
    const int m     = blk >> 2;             // slab 0..575
    const int t     = threadIdx.x;

    const int b       = (m / NH) & 3;       // m = l*48 + b*12 + h
    const int r_first = (4 - (m & 3)) & 3;  // first row with shift 0
    const int Gm      = (785 - r_first) >> 2;
    const int g0      = chunk * GPC;
    int gcnt = Gm - g0;
    if (gcnt > GPC) gcnt = GPC;
    float* gs = &g_sums[b * NP];

    if (t <= 196 && gcnt > 0) {
        const float* fp = att + (size_t)m * SLABSZ
                              + (size_t)(r_first + 4 * g0) * SDIM;   // 16B-aligned

        float a0 = 0.f, a1 = 0.f, a2 = 0.f, a3 = 0.f, a4 = 0.f, a5 = 0.f, a6 = 0.f;

        #pragma unroll 2
        for (int g = 0; g < gcnt; ++g) {
            const float4 x = __ldcs((const float4*)(fp)        + t);  // shift 0
            const float4 y = __ldcs((const float4*)(fp +  784) + t);  // shift 1
            const float4 z = __ldcs((const float4*)(fp + 1568) + t);  // shift 2
            const float4 w = __ldcs((const float4*)(fp + 2352) + t);  // shift 3

            a3 += x.x; a4 += x.y; a5 += x.z; a6 += x.w;   // cols 4t .. 4t+3
            a2 += y.x; a3 += y.y; a4 += y.z; a5 += y.w;   // cols 4t-1 .. 4t+2
            a1 += z.x; a2 += z.y; a3 += z.z; a4 += z.w;   // cols 4t-2 .. 4t+1
            a0 += w.x; a1 += w.y; a2 += w.z; a3 += w.w;   // cols 4t-3 .. 4t
            fp += 4 * SDIM;
        }

        const float acc[7] = {a0, a1, a2, a3, a4, a5, a6};
        const int cbase = 4 * t - 3;
        #pragma unroll
        for (int d = 0; d < 7; ++d) {
            const int c = cbase + d;              // column j in [1,784]
            if (c >= 1 && c <= NP) atomicAdd(&gs[c - 1], acc[d]);
        }
    }

    // Edge-row correction (chunk-3 block only):
    //   m%4==0: groups cover 0..783  -> -row0, +row784
    //   m%4==1: cover 3..782         -> +rows 1,2,783,784
    //   m%4==2: cover 2..781         -> +rows 1,782,783,784
    //   m%4==3: cover 1..784         -> nothing
    if (chunk == CHUNKS - 1) {
        const int mm = m & 3;
        if (mm != 3) {
            const float* base = att + (size_t)m * SLABSZ;
            int   rows[4]; float sgn[4]; int n;
            if (mm == 0)      { rows[0]=0; sgn[0]=-1.f; rows[1]=784; sgn[1]=1.f; n=2; }
            else if (mm == 1) { rows[0]=1; rows[1]=2;   rows[2]=783; rows[3]=784;
                                sgn[0]=sgn[1]=sgn[2]=sgn[3]=1.f; n=4; }
            else              { rows[0]=1; rows[1]=782; rows[2]=783; rows[3]=784;
                                sgn[0]=sgn[1]=sgn[2]=sgn[3]=1.f; n=4; }
            for (int c = t; c < NP; c += blockDim.x) {
                float s = 0.f;
                for (int i = 0; i < n; ++i)
                    s += sgn[i] * __ldg(base + (size_t)rows[i] * SDIM + (c + 1));
                atomicAdd(&gs[c], s);
            }
        }
    }
}

// ---------------------------------------------------------------------------
// Kernel 2: LayerNorm + sigmoid + radix-select kth-smallest + mask.
// p = sigmoid(ln) > 0, so IEEE bits compare like the floats: radix-select
// directly on __float_as_uint(p). 4 passes x 8 bits -> exact kth value.
// ---------------------------------------------------------------------------
__device__ __forceinline__ float block_reduce_sum(float v, float* red) {
    #pragma unroll
    for (int o = 16; o > 0; o >>= 1) v += __shfl_xor_sync(0xFFFFFFFFu, v, o);
    const int wid = threadIdx.x >> 5, lid = threadIdx.x & 31;
    if (lid == 0) red[wid] = v;
    __syncthreads();
    if (wid == 0) {
        v = red[lid];
        #pragma unroll
        for (int o = 16; o > 0; o >>= 1) v += __shfl_xor_sync(0xFFFFFFFFu, v, o);
        if (lid == 0) red[0] = v;
    }
    __syncthreads();
    float r = red[0];
    __syncthreads();
    return r;
}

__global__ __launch_bounds__(1024) void finalize_kernel(const float* __restrict__ gamma,
                                                        const float* __restrict__ beta,
                                                        float* __restrict__ out) {
    __shared__ float red[32];
    __shared__ int   hist[256];
    __shared__ unsigned s_prefix;
    __shared__ int      s_k;

    const int b = blockIdx.x;
    const int t = threadIdx.x;
    const int wid = t >> 5, lid = t & 31;
    const bool active = (t < NP);

    float s = active ? g_sums[b * NP + t] * (1.0f / 144.0f) : 0.0f;

    const float mu = block_reduce_sum(s, red) * (1.0f / (float)NP);
    float d = active ? (s - mu) : 0.0f;
    const float rstd = rsqrtf(block_reduce_sum(d * d, red) * (1.0f / (float)NP) + LN_EPS);

    float p = 0.0f;
    unsigned key = 0u;
    if (active) {
        float ln = d * rstd * gamma[t] + beta[t];
        p   = 1.0f / (1.0f + expf(-ln));
        key = __float_as_uint(p);          // monotone for positive floats
    }

    if (t == 0) { s_prefix = 0u; s_k = KTH; }
    __syncthreads();

    #pragma unroll
    for (int pass = 0; pass < 4; ++pass) {
        const int shift = 24 - 8 * pass;
        const unsigned hi_mask = (pass == 0) ? 0u : (0xFFFFFFFFu << (shift + 8));

        if (t < 256) hist[t] = 0;
        __syncthreads();

        const unsigned prefix = s_prefix;
        const int k = s_k;
        if (active && ((key & hi_mask) == prefix))
            atomicAdd(&hist[(key >> shift) & 255], 1);
        __syncthreads();

        if (wid == 0) {
            int sub = 0;
            #pragma unroll
            for (int i = 0; i < 8; ++i) sub += hist[lid * 8 + i];
            int inc = sub;
            #pragma unroll
            for (int o = 1; o < 32; o <<= 1) {
                int v = __shfl_up_sync(0xFFFFFFFFu, inc, o);
                if (lid >= o) inc += v;
            }
            const int ex = inc - sub;
            if (ex < k && k <= inc) {           // exactly one lane
                int cum = ex;
                #pragma unroll
                for (int i = 0; i < 8; ++i) {
                    const int h = hist[lid * 8 + i];
                    if (k <= cum + h) {
                        s_prefix = prefix | ((unsigned)(lid * 8 + i) << shift);
                        s_k = k - cum;
                        break;
                    }
                    cum += h;
                }
            }
        }
        __syncthreads();
    }

    const float thr = __uint_as_float(s_prefix);   // exact kth-smallest p
    if (active) out[b * NP + t] = (p > thr) ? 1.0f : 0.0f;
}

// ---------------------------------------------------------------------------
// Launch contract
// ---------------------------------------------------------------------------
extern "C" void kernel_launch(void* const* d_in, const int* in_sizes, int n_in,
                              void* d_out, int out_size) {
    const float* att   = (const float*)d_in[0];   // [12,4,12,785,785] f32
    const float* gamma = (const float*)d_in[1];   // [784] f32
    const float* beta  = (const float*)d_in[2];   // [784] f32
    float* out = (float*)d_out;                   // [4,784] f32

    zero_kernel<<<(NB * NP + 255) / 256, 256>>>();
    colsum_vec<<<NSLAB * CHUNKS, 224>>>(att);
    finalize_kernel<<<NB, 1024>>>(gamma, beta, out);
}